// round 8
// baseline (speedup 1.0000x reference)
#include <cuda_runtime.h>
#include <cuda_fp16.h>
#include <cstdint>

#define TOK 2048
#define HD  1536
#define ID  4096
#define NE  8      // 2 shared + 6 routed
#define ER  6
#define N2  (2*ID)   // interleaved gate/up width = 8192

// ---------------- device scratch (static, no allocations) ----------------
__device__ __align__(256) __half g_x16[(size_t)TOK*HD];
__device__ __align__(256) __half g_wgu[(size_t)NE*HD*N2];   // [e][H][2*ID] interleaved
__device__ __align__(256) __half g_wd [(size_t)NE*ID*HD];
__device__ __align__(256) __half g_h  [(size_t)NE*TOK*ID];  // gathered h per expert slot
__device__ int   g_cnt[ER];
__device__ int   g_tok[ER*TOK];
__device__ float g_wslot[ER*TOK];

__device__ __forceinline__ unsigned h2u(__half2 h) {
    return *reinterpret_cast<unsigned*>(&h);
}

// ---------------- init ----------------
__global__ void k_init() {
    if (threadIdx.x < ER) g_cnt[threadIdx.x] = 0;
}

// ---------------- fp32 -> fp16 convert, 8 elems/thread ----------------
// W: 0 -> g_x16, 1 -> g_wd
template<int W>
__global__ void k_cvt8(const float* __restrict__ src, size_t dstOff, long n8) {
    __half* dst = ((W==0) ? g_x16 : g_wd) + dstOff;
    const float4* s4 = (const float4*)src;
    uint4* d4 = (uint4*)dst;
    long i = (long)blockIdx.x*blockDim.x + threadIdx.x;
    long stride = (long)gridDim.x*blockDim.x;
    for (; i < n8; i += stride) {
        float4 a = s4[2*i], b = s4[2*i+1];
        uint4 o;
        o.x = h2u(__floats2half2_rn(a.x, a.y));
        o.y = h2u(__floats2half2_rn(a.z, a.w));
        o.z = h2u(__floats2half2_rn(b.x, b.y));
        o.w = h2u(__floats2half2_rn(b.z, b.w));
        d4[i] = o;
    }
}

// interleave Wg/Wu -> g_wgu: per thread 4 cols of each -> 8 interleaved halves
__global__ void k_cvt_wgu(const float* __restrict__ srcG, const float* __restrict__ srcU,
                          size_t rowOff, long n4 /* float4 groups = rows*ID/4 */) {
    const float4* g4 = (const float4*)srcG;
    const float4* u4 = (const float4*)srcU;
    long i = (long)blockIdx.x*blockDim.x + threadIdx.x;
    long stride = (long)gridDim.x*blockDim.x;
    const long cpr = ID/4;  // float4 groups per row
    for (; i < n4; i += stride) {
        long row = i / cpr, c4 = i - row*cpr;
        float4 g = g4[i], u = u4[i];
        uint4 o;
        o.x = h2u(__floats2half2_rn(g.x, u.x));
        o.y = h2u(__floats2half2_rn(g.y, u.y));
        o.z = h2u(__floats2half2_rn(g.z, u.z));
        o.w = h2u(__floats2half2_rn(g.w, u.w));
        *(uint4*)(g_wgu + (rowOff + row)*(size_t)N2 + 8*c4) = o;
    }
}

// ---------------- router: warp per token, builds per-expert lists ----------------
__global__ void k_router(const float* __restrict__ x, const float* __restrict__ Wr,
                         const float* __restrict__ rb) {
    int t = (blockIdx.x*blockDim.x + threadIdx.x) >> 5;
    int lane = threadIdx.x & 31;
    if (t >= TOK) return;
    const float* xr = x + (size_t)t*HD;
    float acc[ER];
#pragma unroll
    for (int e = 0; e < ER; e++) acc[e] = 0.f;
    for (int h = lane; h < HD; h += 32) {
        float xv = xr[h];
#pragma unroll
        for (int e = 0; e < ER; e++) acc[e] = fmaf(xv, Wr[h*ER + e], acc[e]);
    }
#pragma unroll
    for (int e = 0; e < ER; e++) {
#pragma unroll
        for (int o = 16; o; o >>= 1) acc[e] += __shfl_xor_sync(0xffffffffu, acc[e], o);
    }
    if (lane == 0) {
#pragma unroll
        for (int e = 0; e < ER; e++) acc[e] += rb[e];
        float m = acc[0];
#pragma unroll
        for (int e = 1; e < ER; e++) m = fmaxf(m, acc[e]);
        float p[ER];
#pragma unroll
        for (int e = 0; e < ER; e++) p[e] = expf(acc[e] - m);
        int i0 = 0;
#pragma unroll
        for (int e = 1; e < ER; e++) if (p[e] > p[i0]) i0 = e;
        int i1 = (i0 == 0) ? 1 : 0;
#pragma unroll
        for (int e = 0; e < ER; e++) if (e != i0 && p[e] > p[i1]) i1 = e;
        float s = p[i0] + p[i1];
        int s0 = atomicAdd(&g_cnt[i0], 1);
        g_tok[i0*TOK + s0] = t;  g_wslot[i0*TOK + s0] = p[i0]/s;
        int s1 = atomicAdd(&g_cnt[i1], 1);
        g_tok[i1*TOK + s1] = t;  g_wslot[i1*TOK + s1] = p[i1]/s;
    }
}

// ---------------- GEMM (mma.sync m16n8k16 fp16, fp32 accum) ----------------
#define BM 128
#define BN 128
#define BK 64
#define PA 72
#define PB 136
#define ASTG (BM*PA)            // halves per A stage = 9216
#define BSTG (BK*PB)            // halves per B stage = 8704
#define STGH (ASTG+BSTG)        // halves per stage   = 17920
#define NSTAGE 3
#define SMEMSZ (NSTAGE*STGH*2)  // 107520 bytes

__device__ __forceinline__ void cpa16(uint32_t s, const void* g) {
    asm volatile("cp.async.cg.shared.global [%0], [%1], 16;\n" :: "r"(s), "l"(g));
}
__device__ __forceinline__ void ldm4(uint32_t& r0, uint32_t& r1, uint32_t& r2, uint32_t& r3, uint32_t a) {
    asm volatile("ldmatrix.sync.aligned.m8n8.x4.shared.b16 {%0,%1,%2,%3}, [%4];"
                 : "=r"(r0), "=r"(r1), "=r"(r2), "=r"(r3) : "r"(a));
}
__device__ __forceinline__ void ldm4t(uint32_t& r0, uint32_t& r1, uint32_t& r2, uint32_t& r3, uint32_t a) {
    asm volatile("ldmatrix.sync.aligned.m8n8.x4.trans.shared.b16 {%0,%1,%2,%3}, [%4];"
                 : "=r"(r0), "=r"(r1), "=r"(r2), "=r"(r3) : "r"(a));
}
__device__ __forceinline__ void mma16816(float* c, const uint32_t* a, uint32_t b0, uint32_t b1) {
    asm volatile("mma.sync.aligned.m16n8k16.row.col.f32.f16.f16.f32 "
                 "{%0,%1,%2,%3}, {%4,%5,%6,%7}, {%8,%9}, {%0,%1,%2,%3};"
                 : "+f"(c[0]), "+f"(c[1]), "+f"(c[2]), "+f"(c[3])
                 : "r"(a[0]), "r"(a[1]), "r"(a[2]), "r"(a[3]), "r"(b0), "r"(b1));
}
__device__ __forceinline__ void redv2(float* p, float a, float b) {
    asm volatile("red.global.add.v2.f32 [%0], {%1, %2};" :: "l"(p), "f"(a), "f"(b) : "memory");
}

// MODE 1: fused gate/up: acc cols (even,odd) = (gate, up); h = w*silu(g)*u -> g_h gathered
// MODE 2: down-proj per expert over its slots, scatter red.add into out
template<int MODE>
__global__ void __launch_bounds__(256, 2) k_gemm(float* __restrict__ outp) {
    const int e = blockIdx.z;
    const int cnt = (e < 2) ? TOK : g_cnt[e-2];
    const int mBase = blockIdx.y * BM;
    if (mBase >= cnt) return;

    extern __shared__ __half sh[];
    const int tid = threadIdx.x;
    const int nB = blockIdx.x * BN;

    const __half* A; const __half* B; int lda, ldb, K;
    if (MODE == 1) { A = g_x16;                  lda = HD; B = g_wgu + (size_t)e*HD*N2; ldb = N2; K = HD; }
    else           { A = g_h + (size_t)e*TOK*ID; lda = ID; B = g_wd  + (size_t)e*ID*HD; ldb = HD; K = ID; }

    int aR[4], aC[4], bR[4], bC[4];
#pragma unroll
    for (int i = 0; i < 4; i++) {
        int q = tid + 256*i;
        aR[i] = q >> 3;  aC[i] = (q & 7) * 8;
        bR[i] = q >> 4;  bC[i] = (q & 15) * 8;
    }
    // per-thread A-row base pointers (gather for MODE 1 routed experts)
    const __half* aPtr[4];
#pragma unroll
    for (int i = 0; i < 4; i++) {
        int slot = mBase + aR[i];
        int sc = (slot < cnt) ? slot : (cnt - 1);
        int row = (MODE == 1 && e >= 2) ? g_tok[(e-2)*TOK + sc] : sc;
        aPtr[i] = A + (size_t)row*lda + aC[i];
    }
    uint32_t sbase = (uint32_t)__cvta_generic_to_shared(sh);

    float acc[4][4][4];
#pragma unroll
    for (int mi = 0; mi < 4; mi++)
#pragma unroll
        for (int nt = 0; nt < 4; nt++)
#pragma unroll
            for (int k = 0; k < 4; k++) acc[mi][nt][k] = 0.f;

    const int wid = tid >> 5, lane = tid & 31;
    const int wm = wid >> 2, wn = wid & 3;
    const int nIter = K / BK;

    auto loadStage = [&](int st, int k0) {
        uint32_t base = sbase + (uint32_t)(st*STGH)*2;
#pragma unroll
        for (int i = 0; i < 4; i++)
            cpa16(base + (uint32_t)(aR[i]*PA + aC[i])*2, aPtr[i] + k0);
#pragma unroll
        for (int i = 0; i < 4; i++)
            cpa16(base + (uint32_t)(ASTG + bR[i]*PB + bC[i])*2,
                  B + (size_t)(k0 + bR[i])*ldb + nB + bC[i]);
        asm volatile("cp.async.commit_group;\n");
    };

    // 3-stage pipeline: prime two stages
    loadStage(0, 0);
    loadStage(1, BK);

    int st = 0;                       // stage index of iteration `it`
    for (int it = 0; it < nIter; ++it) {
        // ensure stage `it` is resident. NOTE: with exactly one group outstanding
        // wait_group 1 is a no-op, so the last iteration must use wait_group 0.
        if (it < nIter - 1) asm volatile("cp.async.wait_group 1;\n" ::: "memory");
        else                asm volatile("cp.async.wait_group 0;\n" ::: "memory");
        __syncthreads();   // single barrier: covers load-visibility + buffer reuse

        if (it + 2 < nIter) {
            int ns = st + 2; if (ns >= NSTAGE) ns -= NSTAGE;
            loadStage(ns, (it + 2) * BK);
        }

        uint32_t aoff = sbase + (uint32_t)(st*STGH)*2;
        uint32_t boff = aoff + (uint32_t)ASTG*2;
#pragma unroll
        for (int ks = 0; ks < 4; ++ks) {
            uint32_t af[4][4]; uint32_t bf[4][2];
#pragma unroll
            for (int mi = 0; mi < 4; mi++) {
                int row = wm*64 + mi*16 + (lane & 15);
                int col = ks*16 + 8*(lane >> 4);
                ldm4(af[mi][0], af[mi][1], af[mi][2], af[mi][3],
                     aoff + (uint32_t)(row*PA + col)*2);
            }
#pragma unroll
            for (int nj = 0; nj < 2; nj++) {
                int row = ks*16 + (lane & 15);
                int col = wn*32 + nj*16 + 8*(lane >> 4);
                uint32_t r0, r1, r2, r3;
                ldm4t(r0, r1, r2, r3, boff + (uint32_t)(row*PB + col)*2);
                bf[2*nj][0] = r0; bf[2*nj][1] = r1;
                bf[2*nj+1][0] = r2; bf[2*nj+1][1] = r3;
            }
#pragma unroll
            for (int mi = 0; mi < 4; mi++)
#pragma unroll
                for (int nt = 0; nt < 4; nt++)
                    mma16816(acc[mi][nt], af[mi], bf[nt][0], bf[nt][1]);
        }
        if (++st == NSTAGE) st = 0;
    }

    // ---------------- epilogue ----------------
    const int gid = lane >> 2, t4 = lane & 3;
    if (MODE == 1) {
        __half* hbase = g_h + (size_t)e*TOK*ID;
#pragma unroll
        for (int mi = 0; mi < 4; mi++) {
            int s0 = mBase + wm*64 + mi*16 + gid;
            int s1 = s0 + 8;
            bool v0 = s0 < cnt, v1 = s1 < cnt;
            float w0 = 0.5f, w1 = 0.5f;
            if (e >= 2) {
                if (v0) w0 = g_wslot[(e-2)*TOK + s0];
                if (v1) w1 = g_wslot[(e-2)*TOK + s1];
            }
#pragma unroll
            for (int nt = 0; nt < 4; nt++) {
                int jh = (nB >> 1) + wn*16 + nt*4 + t4;
                if (v0) {
                    float g = acc[mi][nt][0], u = acc[mi][nt][1];
                    hbase[(size_t)s0*ID + jh] = __float2half_rn(w0 * u * g / (1.f + __expf(-g)));
                }
                if (v1) {
                    float g = acc[mi][nt][2], u = acc[mi][nt][3];
                    hbase[(size_t)s1*ID + jh] = __float2half_rn(w1 * u * g / (1.f + __expf(-g)));
                }
            }
        }
    } else {
#pragma unroll
        for (int mi = 0; mi < 4; mi++) {
            int s0 = mBase + wm*64 + mi*16 + gid;
            int s1 = s0 + 8;
            bool v0 = s0 < cnt, v1 = s1 < cnt;
            int t0 = 0, t1 = 0;
            if (e < 2) { t0 = s0; t1 = s1; }
            else {
                if (v0) t0 = g_tok[(e-2)*TOK + s0];
                if (v1) t1 = g_tok[(e-2)*TOK + s1];
            }
#pragma unroll
            for (int nt = 0; nt < 4; nt++) {
                int gn = nB + wn*32 + nt*8 + 2*t4;
                if (v0) redv2(outp + (size_t)t0*HD + gn, acc[mi][nt][0], acc[mi][nt][1]);
                if (v1) redv2(outp + (size_t)t1*HD + gn, acc[mi][nt][2], acc[mi][nt][3]);
            }
        }
    }
}

// ---------------- host ----------------
extern "C" void kernel_launch(void* const* d_in, const int* in_sizes, int n_in,
                              void* d_out, int out_size) {
    const float* x    = (const float*)d_in[0];
    const float* Wg_s = (const float*)d_in[1];
    const float* Wu_s = (const float*)d_in[2];
    const float* Wd_s = (const float*)d_in[3];
    const float* Wg_r = (const float*)d_in[4];
    const float* Wu_r = (const float*)d_in[5];
    const float* Wd_r = (const float*)d_in[6];
    const float* Wr   = (const float*)d_in[7];
    const float* rb   = (const float*)d_in[8];
    float* out = (float*)d_out;

    cudaFuncSetAttribute(k_gemm<1>, cudaFuncAttributeMaxDynamicSharedMemorySize, SMEMSZ);
    cudaFuncSetAttribute(k_gemm<2>, cudaFuncAttributeMaxDynamicSharedMemorySize, SMEMSZ);

    // Fork-join capture topology:
    //   null stream: memset(out), wgu converts -> [wait eRoute] GEMM1 -> [wait eWd] GEMM2
    //   s2:          k_init, x cvt, router [record eRoute], Wd converts [record eWd]
    cudaStream_t s2;
    cudaStreamCreate(&s2);
    cudaEvent_t eFork, eRoute, eWd;
    cudaEventCreateWithFlags(&eFork,  cudaEventDisableTiming);
    cudaEventCreateWithFlags(&eRoute, cudaEventDisableTiming);
    cudaEventCreateWithFlags(&eWd,    cudaEventDisableTiming);

    cudaEventRecord(eFork, 0);
    cudaStreamWaitEvent(s2, eFork, 0);

    // --- null-stream branch: things GEMM1 needs most (long pole: wgu converts)
    cudaMemsetAsync(out, 0, (size_t)out_size * sizeof(float), 0);
    k_cvt_wgu<<<2048, 256, 0, 0>>>(Wg_s, Wu_s, 0,     2L*HD*(ID/4));
    k_cvt_wgu<<<2048, 256, 0, 0>>>(Wg_r, Wu_r, 2L*HD, 6L*HD*(ID/4));

    // --- side branch: router prerequisites, then Wd (only needed by GEMM2)
    k_init<<<1, 32, 0, s2>>>();
    k_cvt8<0><<<384, 256, 0, s2>>>(x, 0, (long)TOK*HD/8);
    k_router<<<TOK/8, 256, 0, s2>>>(x, Wr, rb);
    cudaEventRecord(eRoute, s2);
    k_cvt8<1><<<2048, 256, 0, s2>>>(Wd_s, 0,                  2L*ID*HD/8);
    k_cvt8<1><<<2048, 256, 0, s2>>>(Wd_r, (size_t)(2L*ID*HD), 6L*ID*HD/8);
    cudaEventRecord(eWd, s2);

    // --- GEMM1 (overlaps with Wd converts on s2)
    cudaStreamWaitEvent(0, eRoute, 0);
    dim3 g1(N2/BN, TOK/BM, NE);    // 64 x 16 x 8 (early-exit on empty tiles)
    k_gemm<1><<<g1, 256, SMEMSZ, 0>>>(nullptr);

    // --- GEMM2
    cudaStreamWaitEvent(0, eWd, 0);
    dim3 g2(HD/BN, TOK/BM, NE);    // 12 x 16 x 8
    k_gemm<2><<<g2, 256, SMEMSZ, 0>>>(out);

    cudaEventDestroy(eFork);
    cudaEventDestroy(eRoute);
    cudaEventDestroy(eWd);
    cudaStreamDestroy(s2);
}

// round 10
// speedup vs baseline: 1.4292x; 1.4292x over previous
#include <cuda_runtime.h>
#include <cuda_fp16.h>
#include <cstdint>

#define TOK 2048
#define HD  1536
#define ID  4096
#define NE  8      // 2 shared + 6 routed
#define ER  6
#define N2  (2*ID)   // interleaved gate/up width = 8192

// ---------------- device scratch (static, no allocations) ----------------
__device__ __align__(256) __half g_x16[(size_t)TOK*HD];
__device__ __align__(256) __half g_wgu[(size_t)NE*HD*N2];   // [e][H][2*ID] interleaved
__device__ __align__(256) __half g_wd [(size_t)NE*ID*HD];
__device__ __align__(256) __half g_h  [(size_t)NE*TOK*ID];  // gathered h per expert slot
__device__ int   g_cnt[ER];
__device__ int   g_tok[ER*TOK];
__device__ float g_wslot[ER*TOK];
// persistent-queue state
__device__ int   g_mte[128];   // m-tile -> expert
__device__ int   g_mtm[128];   // m-tile -> mBase (slot offset)
__device__ int   g_nmt;
__device__ int   g_ctr[2];

#define NWORK 304          // persistent CTAs (2 per SM on 152 SMs)
#define WDCH  768          // Wd convert chunks appended to GEMM1 queue
#define CHF4  16384        // float4 groups per chunk (768*16384 = 8*ID*HD/4 exactly)
#define NS4   (2L*ID*HD/4) // float4 groups in shared Wd (divisible by CHF4)

__device__ __forceinline__ unsigned h2u(__half2 h) {
    return *reinterpret_cast<unsigned*>(&h);
}

// ---------------- init ----------------
__global__ void k_init() {
    if (threadIdx.x < ER) g_cnt[threadIdx.x] = 0;
}

// ---------------- x fp32 -> fp16 ----------------
__global__ void k_cvt_x(const float* __restrict__ src, long n8) {
    const float4* s4 = (const float4*)src;
    uint4* d4 = (uint4*)g_x16;
    long i = (long)blockIdx.x*blockDim.x + threadIdx.x;
    long stride = (long)gridDim.x*blockDim.x;
    for (; i < n8; i += stride) {
        float4 a = s4[2*i], b = s4[2*i+1];
        uint4 o;
        o.x = h2u(__floats2half2_rn(a.x, a.y));
        o.y = h2u(__floats2half2_rn(a.z, a.w));
        o.z = h2u(__floats2half2_rn(b.x, b.y));
        o.w = h2u(__floats2half2_rn(b.z, b.w));
        d4[i] = o;
    }
}

// interleave Wg/Wu -> g_wgu: per thread 4 cols of each -> 8 interleaved halves
__global__ void k_cvt_wgu(const float* __restrict__ srcG, const float* __restrict__ srcU,
                          size_t rowOff, long n4 /* float4 groups = rows*ID/4 */) {
    const float4* g4 = (const float4*)srcG;
    const float4* u4 = (const float4*)srcU;
    long i = (long)blockIdx.x*blockDim.x + threadIdx.x;
    long stride = (long)gridDim.x*blockDim.x;
    const long cpr = ID/4;  // float4 groups per row
    for (; i < n4; i += stride) {
        long row = i / cpr, c4 = i - row*cpr;
        float4 g = g4[i], u = u4[i];
        uint4 o;
        o.x = h2u(__floats2half2_rn(g.x, u.x));
        o.y = h2u(__floats2half2_rn(g.y, u.y));
        o.z = h2u(__floats2half2_rn(g.z, u.z));
        o.w = h2u(__floats2half2_rn(g.w, u.w));
        *(uint4*)(g_wgu + (rowOff + row)*(size_t)N2 + 8*c4) = o;
    }
}

// ---------------- router: warp per token, builds per-expert lists ----------------
__global__ void k_router(const float* __restrict__ x, const float* __restrict__ Wr,
                         const float* __restrict__ rb) {
    int t = (blockIdx.x*blockDim.x + threadIdx.x) >> 5;
    int lane = threadIdx.x & 31;
    if (t >= TOK) return;
    const float* xr = x + (size_t)t*HD;
    float acc[ER];
#pragma unroll
    for (int e = 0; e < ER; e++) acc[e] = 0.f;
    for (int h = lane; h < HD; h += 32) {
        float xv = xr[h];
#pragma unroll
        for (int e = 0; e < ER; e++) acc[e] = fmaf(xv, Wr[h*ER + e], acc[e]);
    }
#pragma unroll
    for (int e = 0; e < ER; e++) {
#pragma unroll
        for (int o = 16; o; o >>= 1) acc[e] += __shfl_xor_sync(0xffffffffu, acc[e], o);
    }
    if (lane == 0) {
#pragma unroll
        for (int e = 0; e < ER; e++) acc[e] += rb[e];
        float m = acc[0];
#pragma unroll
        for (int e = 1; e < ER; e++) m = fmaxf(m, acc[e]);
        float p[ER];
#pragma unroll
        for (int e = 0; e < ER; e++) p[e] = expf(acc[e] - m);
        int i0 = 0;
#pragma unroll
        for (int e = 1; e < ER; e++) if (p[e] > p[i0]) i0 = e;
        int i1 = (i0 == 0) ? 1 : 0;
#pragma unroll
        for (int e = 0; e < ER; e++) if (e != i0 && p[e] > p[i1]) i1 = e;
        float s = p[i0] + p[i1];
        int s0 = atomicAdd(&g_cnt[i0], 1);
        g_tok[i0*TOK + s0] = t;  g_wslot[i0*TOK + s0] = p[i0]/s;
        int s1 = atomicAdd(&g_cnt[i1], 1);
        g_tok[i1*TOK + s1] = t;  g_wslot[i1*TOK + s1] = p[i1]/s;
    }
}

// ---------------- planner: build exact m-tile table, zero counters ----------------
#define BM 128
__global__ void k_plan() {
    if (threadIdx.x == 0) {
        int nm = 0;
        for (int e = 0; e < NE; e++) {
            int cnt = (e < 2) ? TOK : g_cnt[e-2];
            for (int m = 0; m < cnt; m += BM) { g_mte[nm] = e; g_mtm[nm] = m; nm++; }
        }
        g_nmt = nm;
        g_ctr[0] = 0;
        g_ctr[1] = 0;
    }
}

// ---------------- GEMM (mma.sync m16n8k16 fp16, fp32 accum) ----------------
#define BN 128
#define BK 64
#define PA 72
#define PB 136
#define ASTG (BM*PA)            // halves per A stage = 9216
#define BSTG (BK*PB)            // halves per B stage = 8704
#define STGH (ASTG+BSTG)        // halves per stage   = 17920
#define NSTAGE 3
#define SMEMSZ (NSTAGE*STGH*2)  // 107520 bytes

__device__ __forceinline__ void cpa16(uint32_t s, const void* g) {
    asm volatile("cp.async.cg.shared.global [%0], [%1], 16;\n" :: "r"(s), "l"(g));
}
__device__ __forceinline__ void ldm4(uint32_t& r0, uint32_t& r1, uint32_t& r2, uint32_t& r3, uint32_t a) {
    asm volatile("ldmatrix.sync.aligned.m8n8.x4.shared.b16 {%0,%1,%2,%3}, [%4];"
                 : "=r"(r0), "=r"(r1), "=r"(r2), "=r"(r3) : "r"(a));
}
__device__ __forceinline__ void ldm4t(uint32_t& r0, uint32_t& r1, uint32_t& r2, uint32_t& r3, uint32_t a) {
    asm volatile("ldmatrix.sync.aligned.m8n8.x4.trans.shared.b16 {%0,%1,%2,%3}, [%4];"
                 : "=r"(r0), "=r"(r1), "=r"(r2), "=r"(r3) : "r"(a));
}
__device__ __forceinline__ void mma16816(float* c, const uint32_t* a, uint32_t b0, uint32_t b1) {
    asm volatile("mma.sync.aligned.m16n8k16.row.col.f32.f16.f16.f32 "
                 "{%0,%1,%2,%3}, {%4,%5,%6,%7}, {%8,%9}, {%0,%1,%2,%3};"
                 : "+f"(c[0]), "+f"(c[1]), "+f"(c[2]), "+f"(c[3])
                 : "r"(a[0]), "r"(a[1]), "r"(a[2]), "r"(a[3]), "r"(b0), "r"(b1));
}
__device__ __forceinline__ void redv2(float* p, float a, float b) {
    asm volatile("red.global.add.v2.f32 [%0], {%1, %2};" :: "l"(p), "f"(a), "f"(b) : "memory");
}

// Persistent work-queue GEMM.
// MODE 1: items [0,nmt*64)  = fused gate/up tiles -> g_h;  items [nmt*64, +WDCH) = Wd fp32->fp16 chunks
// MODE 2: items [0,nmt*12)  = down-proj tiles, red.add scatter into out
template<int MODE>
__global__ void __launch_bounds__(256, 2) k_gemm(float* __restrict__ outp,
                                                 const float* __restrict__ wdS,
                                                 const float* __restrict__ wdR) {
    extern __shared__ __half sh[];
    __shared__ int s_item;
    const int tid = threadIdx.x;
    const int wid = tid >> 5, lane = tid & 31;
    const int wm = wid >> 2, wn = wid & 3;
    const uint32_t sbase = (uint32_t)__cvta_generic_to_shared(sh);

    constexpr int NBX   = (MODE == 1) ? (N2/BN) : (HD/BN);   // 64 : 12
    constexpr int K     = (MODE == 1) ? HD : ID;
    constexpr int nIter = K / BK;

    const int nmt  = g_nmt;
    const int nT   = nmt * NBX;
    const int nTot = (MODE == 1) ? nT + WDCH : nT;

    // per-thread load coords (tid-only; hoisted out of the work loop)
    int aR[4], aC[4], bR[4], bC[4];
#pragma unroll
    for (int i = 0; i < 4; i++) {
        int q = tid + 256*i;
        aR[i] = q >> 3;  aC[i] = (q & 7) * 8;
        bR[i] = q >> 4;  bC[i] = (q & 15) * 8;
    }

    for (;;) {
        if (tid == 0) s_item = atomicAdd(&g_ctr[MODE-1], 1);
        __syncthreads();                       // publish s_item; also guards smem reuse
        const int item = s_item;
        if (item >= nTot) return;

        if (item < nT) {
            // ---------------- GEMM tile ----------------
            const int mt = (MODE == 1) ? (item >> 6) : (item / NBX);
            const int bx = item - mt*NBX;
            const int e = g_mte[mt], mBase = g_mtm[mt];
            const int cnt = (e < 2) ? TOK : g_cnt[e-2];
            const int nB = bx * BN;

            const __half* A; const __half* B; int lda, ldb;
            if (MODE == 1) { A = g_x16;                  lda = HD; B = g_wgu + (size_t)e*HD*N2; ldb = N2; }
            else           { A = g_h + (size_t)e*TOK*ID; lda = ID; B = g_wd  + (size_t)e*ID*HD; ldb = HD; }

            const __half* aPtr[4];
#pragma unroll
            for (int i = 0; i < 4; i++) {
                int slot = mBase + aR[i];
                int sc = (slot < cnt) ? slot : (cnt - 1);
                int row = (MODE == 1 && e >= 2) ? g_tok[(e-2)*TOK + sc] : sc;
                aPtr[i] = A + (size_t)row*lda + aC[i];
            }

            float acc[4][4][4];
#pragma unroll
            for (int mi = 0; mi < 4; mi++)
#pragma unroll
                for (int nt = 0; nt < 4; nt++)
#pragma unroll
                    for (int k = 0; k < 4; k++) acc[mi][nt][k] = 0.f;

            auto loadStage = [&](int st, int k0) {
                uint32_t base = sbase + (uint32_t)(st*STGH)*2;
#pragma unroll
                for (int i = 0; i < 4; i++)
                    cpa16(base + (uint32_t)(aR[i]*PA + aC[i])*2, aPtr[i] + k0);
#pragma unroll
                for (int i = 0; i < 4; i++)
                    cpa16(base + (uint32_t)(ASTG + bR[i]*PB + bC[i])*2,
                          B + (size_t)(k0 + bR[i])*ldb + nB + bC[i]);
                asm volatile("cp.async.commit_group;\n");
            };

            loadStage(0, 0);
            loadStage(1, BK);

            int st = 0;
            for (int it = 0; it < nIter; ++it) {
                if (it < nIter - 1) asm volatile("cp.async.wait_group 1;\n" ::: "memory");
                else                asm volatile("cp.async.wait_group 0;\n" ::: "memory");
                __syncthreads();

                if (it + 2 < nIter) {
                    int ns = st + 2; if (ns >= NSTAGE) ns -= NSTAGE;
                    loadStage(ns, (it + 2) * BK);
                }

                uint32_t aoff = sbase + (uint32_t)(st*STGH)*2;
                uint32_t boff = aoff + (uint32_t)ASTG*2;
#pragma unroll
                for (int ks = 0; ks < 4; ++ks) {
                    uint32_t af[4][4]; uint32_t bf[4][2];
#pragma unroll
                    for (int mi = 0; mi < 4; mi++) {
                        int row = wm*64 + mi*16 + (lane & 15);
                        int col = ks*16 + 8*(lane >> 4);
                        ldm4(af[mi][0], af[mi][1], af[mi][2], af[mi][3],
                             aoff + (uint32_t)(row*PA + col)*2);
                    }
#pragma unroll
                    for (int nj = 0; nj < 2; nj++) {
                        int row = ks*16 + (lane & 15);
                        int col = wn*32 + nj*16 + 8*(lane >> 4);
                        uint32_t r0, r1, r2, r3;
                        ldm4t(r0, r1, r2, r3, boff + (uint32_t)(row*PB + col)*2);
                        bf[2*nj][0] = r0; bf[2*nj][1] = r1;
                        bf[2*nj+1][0] = r2; bf[2*nj+1][1] = r3;
                    }
#pragma unroll
                    for (int mi = 0; mi < 4; mi++)
#pragma unroll
                        for (int nt = 0; nt < 4; nt++)
                            mma16816(acc[mi][nt], af[mi], bf[nt][0], bf[nt][1]);
                }
                if (++st == NSTAGE) st = 0;
            }

            // ---------------- epilogue ----------------
            const int gid = lane >> 2, t4 = lane & 3;
            if (MODE == 1) {
                __half* hbase = g_h + (size_t)e*TOK*ID;
#pragma unroll
                for (int mi = 0; mi < 4; mi++) {
                    int s0 = mBase + wm*64 + mi*16 + gid;
                    int s1 = s0 + 8;
                    bool v0 = s0 < cnt, v1 = s1 < cnt;
                    float w0 = 0.5f, w1 = 0.5f;
                    if (e >= 2) {
                        if (v0) w0 = g_wslot[(e-2)*TOK + s0];
                        if (v1) w1 = g_wslot[(e-2)*TOK + s1];
                    }
#pragma unroll
                    for (int nt = 0; nt < 4; nt++) {
                        int jh = (nB >> 1) + wn*16 + nt*4 + t4;
                        if (v0) {
                            float g = acc[mi][nt][0], u = acc[mi][nt][1];
                            hbase[(size_t)s0*ID + jh] = __float2half_rn(w0 * u * g / (1.f + __expf(-g)));
                        }
                        if (v1) {
                            float g = acc[mi][nt][2], u = acc[mi][nt][3];
                            hbase[(size_t)s1*ID + jh] = __float2half_rn(w1 * u * g / (1.f + __expf(-g)));
                        }
                    }
                }
            } else {
#pragma unroll
                for (int mi = 0; mi < 4; mi++) {
                    int s0 = mBase + wm*64 + mi*16 + gid;
                    int s1 = s0 + 8;
                    bool v0 = s0 < cnt, v1 = s1 < cnt;
                    int t0 = 0, t1 = 0;
                    if (e < 2) { t0 = s0; t1 = s1; }
                    else {
                        if (v0) t0 = g_tok[(e-2)*TOK + s0];
                        if (v1) t1 = g_tok[(e-2)*TOK + s1];
                    }
#pragma unroll
                    for (int nt = 0; nt < 4; nt++) {
                        int gn = nB + wn*32 + nt*8 + 2*t4;
                        if (v0) redv2(outp + (size_t)t0*HD + gn, acc[mi][nt][0], acc[mi][nt][1]);
                        if (v1) redv2(outp + (size_t)t1*HD + gn, acc[mi][nt][2], acc[mi][nt][3]);
                    }
                }
            }
        } else if (MODE == 1) {
            // ---------------- Wd fp32->fp16 chunk (tail filler) ----------------
            const long base = (long)(item - nT) * CHF4;   // f4 index into 8-expert Wd
            const float4* src; long off;
            if (base < NS4) { src = (const float4*)wdS; off = base; }
            else            { src = (const float4*)wdR; off = base - NS4; }
            uint4* d4 = (uint4*)g_wd;
            const long o2 = base >> 1;                    // uint4 output index
#pragma unroll 4
            for (int i = tid; i < CHF4/2; i += 256) {
                float4 a = src[off + 2*i], b = src[off + 2*i + 1];
                uint4 o;
                o.x = h2u(__floats2half2_rn(a.x, a.y));
                o.y = h2u(__floats2half2_rn(a.z, a.w));
                o.z = h2u(__floats2half2_rn(b.x, b.y));
                o.w = h2u(__floats2half2_rn(b.z, b.w));
                d4[o2 + i] = o;
            }
        }
        __syncthreads();   // all smem reads done before next item's s_item write / loads
    }
}

// ---------------- host ----------------
extern "C" void kernel_launch(void* const* d_in, const int* in_sizes, int n_in,
                              void* d_out, int out_size) {
    const float* x    = (const float*)d_in[0];
    const float* Wg_s = (const float*)d_in[1];
    const float* Wu_s = (const float*)d_in[2];
    const float* Wd_s = (const float*)d_in[3];
    const float* Wg_r = (const float*)d_in[4];
    const float* Wu_r = (const float*)d_in[5];
    const float* Wd_r = (const float*)d_in[6];
    const float* Wr   = (const float*)d_in[7];
    const float* rb   = (const float*)d_in[8];
    float* out = (float*)d_out;

    cudaMemsetAsync(out, 0, (size_t)out_size * sizeof(float));
    k_init<<<1, 32>>>();

    k_cvt_x<<<384, 256>>>(x, (long)TOK*HD/8);
    k_router<<<TOK/8, 256>>>(x, Wr, rb);
    k_plan<<<1, 32>>>();

    k_cvt_wgu<<<2048, 256>>>(Wg_s, Wu_s, 0,     2L*HD*(ID/4));
    k_cvt_wgu<<<2048, 256>>>(Wg_r, Wu_r, 2L*HD, 6L*HD*(ID/4));

    cudaFuncSetAttribute(k_gemm<1>, cudaFuncAttributeMaxDynamicSharedMemorySize, SMEMSZ);
    cudaFuncSetAttribute(k_gemm<2>, cudaFuncAttributeMaxDynamicSharedMemorySize, SMEMSZ);

    // GEMM1 queue: gate/up tiles then Wd-convert chunks (tail filler)
    k_gemm<1><<<NWORK, 256, SMEMSZ>>>(nullptr, Wd_s, Wd_r);
    // GEMM2 queue: down-proj tiles
    k_gemm<2><<<NWORK, 256, SMEMSZ>>>(out, nullptr, nullptr);
}